// round 7
// baseline (speedup 1.0000x reference)
#include <cuda_runtime.h>
#include <math.h>

#define DIM 2048
#define HID 8192
#define MAX_LEN 8192
#define NBLK_ATTN 256
#define NW_ATTN (NBLK_ATTN * 8)          // 2048 warps = row stride
#define MAXI (MAX_LEN / NW_ATTN + 1)     // 5 row-chunks per warp max

// ---------------- scratch ----------------
__device__ float g_qkv[3 * DIM];               // q | k | v
__device__ float g_psum[NBLK_ATTN];            // per-block sum of exp
__device__ float g_invZ;                       // 1/sum(exp)
__device__ unsigned g_cnt;                     // last-block counter (self-resetting)
__device__ float g_partial[NBLK_ATTN * DIM];   // per-block weighted V partials
__device__ float g_attn[DIM];                  // normalized attention output
__device__ float g_x2[DIM];                    // x + attn@oW + ob
__device__ float g_h[HID];                     // gelu(fc1)

// ---------------- kernel 1: fused rmsnorm + QKV GEMV ----------------
__global__ void k_qkv(const float* __restrict__ x, const float* __restrict__ anw,
                      const float* __restrict__ qw, const float* __restrict__ qb,
                      const float* __restrict__ kw, const float* __restrict__ kb,
                      const float* __restrict__ vw, const float* __restrict__ vb) {
    __shared__ float s_xn[DIM];
    __shared__ float s_red[8];
    __shared__ float s_inv;
    int tid = threadIdx.x, warp = tid >> 5, lane = tid & 31;

    const float4* x4 = reinterpret_cast<const float4*>(x);
    float4 v0 = x4[tid], v1 = x4[tid + 256];
    float ss = v0.x*v0.x + v0.y*v0.y + v0.z*v0.z + v0.w*v0.w
             + v1.x*v1.x + v1.y*v1.y + v1.z*v1.z + v1.w*v1.w;
#pragma unroll
    for (int o = 16; o > 0; o >>= 1) ss += __shfl_xor_sync(0xffffffffu, ss, o);
    if (lane == 0) s_red[warp] = ss;
    __syncthreads();
    if (tid == 0) {
        float t = 0.f;
#pragma unroll
        for (int i = 0; i < 8; i++) t += s_red[i];
        s_inv = rsqrtf(t * (1.f / DIM) + 1e-6f);
    }
    __syncthreads();
    float inv = s_inv;
    const float4* a4 = reinterpret_cast<const float4*>(anw);
    float4 n0 = a4[tid], n1 = a4[tid + 256];
    float4* sx4 = reinterpret_cast<float4*>(s_xn);
    sx4[tid]       = make_float4(v0.x*inv*n0.x, v0.y*inv*n0.y, v0.z*inv*n0.z, v0.w*inv*n0.w);
    sx4[tid + 256] = make_float4(v1.x*inv*n1.x, v1.y*inv*n1.y, v1.z*inv*n1.z, v1.w*inv*n1.w);
    __syncthreads();

    int r = blockIdx.x * 8 + warp;          // 0..6143
    int m = r >> 11;
    int j = r & (DIM - 1);
    const float* W = (m == 0) ? qw : (m == 1) ? kw : vw;
    const float* B = (m == 0) ? qb : (m == 1) ? kb : vb;
    const float4* w4 = reinterpret_cast<const float4*>(W + (size_t)j * DIM);
    float acc = 0.f;
#pragma unroll 8
    for (int i = lane; i < DIM / 4; i += 32) {
        float4 a = w4[i]; float4 b = sx4[i];
        acc += a.x*b.x + a.y*b.y + a.z*b.z + a.w*b.w;
    }
#pragma unroll
    for (int o = 16; o > 0; o >>= 1) acc += __shfl_xor_sync(0xffffffffu, acc, o);
    if (lane == 0) g_qkv[r] = acc + B[j];
}

// ---------------- kernel 2: fused scores + exp + weighted-V partials ----------------
// 256 blocks x 256 thr. Warp w of block b owns rows b*8+w, +2048, +4096, ...
// Phase A: e = exp(K_r . q / sqrt(d)) for own rows -> smem.
// Phase B: partial[d] = sum over own rows of e_r * V[r][d]  (thread owns 8 dims).
// Z computed by fenced-counter last block.
__global__ void k_attn(const float* __restrict__ cacheK,
                       const float* __restrict__ cacheV,
                       const int* __restrict__ posp) {
    __shared__ float s_q[DIM];
    __shared__ float s_e[MAXI][8];
    __shared__ bool s_last;
    int pos = *posp;
    int tid = threadIdx.x, warp = tid >> 5, lane = tid & 31;

    float4* sq4 = reinterpret_cast<float4*>(s_q);
    const float4* q4 = reinterpret_cast<const float4*>(g_qkv);
    sq4[tid] = q4[tid];
    sq4[tid + 256] = q4[tid + 256];
    if (tid < MAXI * 8) ((float*)s_e)[tid] = 0.f;
    __syncthreads();

    // Phase A: scores -> exp
#pragma unroll
    for (int i = 0; i < MAXI; i++) {
        int r = blockIdx.x * 8 + warp + i * NW_ATTN;
        if (r <= pos) {
            const float* krow = (r == pos) ? (g_qkv + DIM)
                                           : (cacheK + (size_t)r * DIM);
            const float4* k4 = reinterpret_cast<const float4*>(krow);
            float acc = 0.f;
#pragma unroll 8
            for (int c = lane; c < DIM / 4; c += 32) {
                float4 a = k4[c]; float4 b = sq4[c];
                acc += a.x*b.x + a.y*b.y + a.z*b.z + a.w*b.w;
            }
#pragma unroll
            for (int o = 16; o > 0; o >>= 1) acc += __shfl_xor_sync(0xffffffffu, acc, o);
            if (lane == 0)
                s_e[i][warp] = __expf(acc * 0.022097086912079608f);  // 1/sqrt(2048)
        }
    }
    __syncthreads();

    // per-block psum + last-block election (deterministic fixed-order sums)
    if (tid == 0) {
        float s = 0.f;
#pragma unroll
        for (int i = 0; i < MAXI * 8; i++) s += ((float*)s_e)[i];
        g_psum[blockIdx.x] = s;
        __threadfence();
        unsigned old = atomicAdd(&g_cnt, 1u);
        s_last = (old == (unsigned)(gridDim.x - 1));
    }

    // Phase B: weighted V accumulation (thread owns dims 8*tid .. 8*tid+7)
    float4 acc0 = make_float4(0.f, 0.f, 0.f, 0.f);
    float4 acc1 = make_float4(0.f, 0.f, 0.f, 0.f);
#pragma unroll
    for (int i = 0; i < MAXI; i++) {
#pragma unroll
        for (int w = 0; w < 8; w++) {
            int r = blockIdx.x * 8 + w + i * NW_ATTN;
            if (r <= pos) {
                float p = s_e[i][w];
                const float* vrow = (r == pos) ? (g_qkv + 2 * DIM)
                                               : (cacheV + (size_t)r * DIM);
                const float4* v4 = reinterpret_cast<const float4*>(vrow) + tid * 2;
                float4 a = v4[0], b = v4[1];
                acc0.x += p * a.x; acc0.y += p * a.y; acc0.z += p * a.z; acc0.w += p * a.w;
                acc1.x += p * b.x; acc1.y += p * b.y; acc1.z += p * b.z; acc1.w += p * b.w;
            }
        }
    }
    float4* p4 = reinterpret_cast<float4*>(g_partial + (size_t)blockIdx.x * DIM) + tid * 2;
    p4[0] = acc0;
    p4[1] = acc1;

    // last block computes 1/Z over the 256 psums
    __syncthreads();
    if (s_last) {
        __threadfence();
        float z = (tid < NBLK_ATTN) ? g_psum[tid] : 0.f;
#pragma unroll
        for (int o = 16; o > 0; o >>= 1) z += __shfl_xor_sync(0xffffffffu, z, o);
        __shared__ float s_z[8];
        if (lane == 0) s_z[warp] = z;
        __syncthreads();
        if (tid == 0) {
            float t = 0.f;
#pragma unroll
            for (int i = 0; i < 8; i++) t += s_z[i];
            g_invZ = 1.f / t;
            g_cnt = 0;                      // reset for next graph replay
        }
    }
}

// ---------------- kernel 3: reduce 256 partials (8 thr/dim, MLP=32) + 1/Z ----------------
__global__ void k_attnv_reduce() {
    int tid = threadIdx.x;
    int d = blockIdx.x * 32 + (tid >> 3);
    int q = tid & 7;
    float acc = 0.f;
#pragma unroll
    for (int k = 0; k < NBLK_ATTN / 8; k++)
        acc += g_partial[(size_t)(q + 8 * k) * DIM + d];
    acc += __shfl_xor_sync(0xffffffffu, acc, 1);
    acc += __shfl_xor_sync(0xffffffffu, acc, 2);
    acc += __shfl_xor_sync(0xffffffffu, acc, 4);
    if (q == 0) g_attn[d] = acc * g_invZ;
}

// ---------------- kernel 4: o-proj + residual (4 rows/blk, 2 warps/row) ----------------
__global__ void k_oproj(const float* __restrict__ ow, const float* __restrict__ ob,
                        const float* __restrict__ x) {
    __shared__ float s_a[DIM];
    __shared__ float s_part[4][2];
    int tid = threadIdx.x, warp = tid >> 5, lane = tid & 31;
    float4* sa4 = reinterpret_cast<float4*>(s_a);
    const float4* g4 = reinterpret_cast<const float4*>(g_attn);
    sa4[tid] = g4[tid];
    sa4[tid + 256] = g4[tid + 256];
    __syncthreads();

    int rl = warp >> 1, wp = warp & 1;
    int row = blockIdx.x * 4 + rl;
    const float4* w4 = reinterpret_cast<const float4*>(ow + (size_t)row * DIM);
    float acc = 0.f;
    int base = wp * 256;
#pragma unroll 8
    for (int i = base + lane; i < base + 256; i += 32) {
        float4 a = w4[i]; float4 b = sa4[i];
        acc += a.x*b.x + a.y*b.y + a.z*b.z + a.w*b.w;
    }
#pragma unroll
    for (int o = 16; o > 0; o >>= 1) acc += __shfl_xor_sync(0xffffffffu, acc, o);
    if (lane == 0) s_part[rl][wp] = acc;
    __syncthreads();
    if (tid < 4) {
        int r = blockIdx.x * 4 + tid;
        g_x2[r] = x[r] + s_part[tid][0] + s_part[tid][1] + ob[r];
    }
}

// ---------------- kernel 5: fused rmsnorm + fc1 + exact GELU ----------------
__global__ void k_fc1(const float* __restrict__ mnw,
                      const float* __restrict__ w1, const float* __restrict__ b1) {
    __shared__ float s_xn[DIM];
    __shared__ float s_red[8];
    __shared__ float s_inv;
    int tid = threadIdx.x, warp = tid >> 5, lane = tid & 31;

    const float4* x4 = reinterpret_cast<const float4*>(g_x2);
    float4 v0 = x4[tid], v1 = x4[tid + 256];
    float ss = v0.x*v0.x + v0.y*v0.y + v0.z*v0.z + v0.w*v0.w
             + v1.x*v1.x + v1.y*v1.y + v1.z*v1.z + v1.w*v1.w;
#pragma unroll
    for (int o = 16; o > 0; o >>= 1) ss += __shfl_xor_sync(0xffffffffu, ss, o);
    if (lane == 0) s_red[warp] = ss;
    __syncthreads();
    if (tid == 0) {
        float t = 0.f;
#pragma unroll
        for (int i = 0; i < 8; i++) t += s_red[i];
        s_inv = rsqrtf(t * (1.f / DIM) + 1e-6f);
    }
    __syncthreads();
    float inv = s_inv;
    const float4* m4 = reinterpret_cast<const float4*>(mnw);
    float4 n0 = m4[tid], n1 = m4[tid + 256];
    float4* sx4 = reinterpret_cast<float4*>(s_xn);
    sx4[tid]       = make_float4(v0.x*inv*n0.x, v0.y*inv*n0.y, v0.z*inv*n0.z, v0.w*inv*n0.w);
    sx4[tid + 256] = make_float4(v1.x*inv*n1.x, v1.y*inv*n1.y, v1.z*inv*n1.z, v1.w*inv*n1.w);
    __syncthreads();

    int row = blockIdx.x * 8 + warp;           // 0..8191
    const float4* w4 = reinterpret_cast<const float4*>(w1 + (size_t)row * DIM);
    float acc = 0.f;
#pragma unroll 8
    for (int i = lane; i < DIM / 4; i += 32) {
        float4 a = w4[i]; float4 b = sx4[i];
        acc += a.x*b.x + a.y*b.y + a.z*b.z + a.w*b.w;
    }
#pragma unroll
    for (int o = 16; o > 0; o >>= 1) acc += __shfl_xor_sync(0xffffffffu, acc, o);
    if (lane == 0) {
        float v = acc + b1[row];
        g_h[row] = 0.5f * v * (1.f + erff(v * 0.70710678118654752f));
    }
}

// ---------------- kernel 6: fc2 + residual -> out (4 rows/blk, 2 warps/row) ----------------
__global__ void k_fc2(const float* __restrict__ w2, const float* __restrict__ b2,
                      float* __restrict__ out) {
    __shared__ float s_h[HID];
    __shared__ float s_part[4][2];
    int tid = threadIdx.x, warp = tid >> 5, lane = tid & 31;
    float4* sh4 = reinterpret_cast<float4*>(s_h);
    const float4* h4 = reinterpret_cast<const float4*>(g_h);
#pragma unroll
    for (int i = 0; i < 8; i++) sh4[tid + 256 * i] = h4[tid + 256 * i];
    __syncthreads();

    int rl = warp >> 1, wp = warp & 1;
    int row = blockIdx.x * 4 + rl;
    const float4* w4 = reinterpret_cast<const float4*>(w2 + (size_t)row * HID);
    float acc = 0.f;
    int base = wp * 1024;
#pragma unroll 8
    for (int i = base + lane; i < base + 1024; i += 32) {
        float4 a = w4[i]; float4 b = sh4[i];
        acc += a.x*b.x + a.y*b.y + a.z*b.z + a.w*b.w;
    }
#pragma unroll
    for (int o = 16; o > 0; o >>= 1) acc += __shfl_xor_sync(0xffffffffu, acc, o);
    if (lane == 0) s_part[rl][wp] = acc;
    __syncthreads();
    if (tid < 4) {
        int r = blockIdx.x * 4 + tid;
        out[r] = g_x2[r] + s_part[tid][0] + s_part[tid][1] + b2[r];
    }
}

// ---------------- launch ----------------
extern "C" void kernel_launch(void* const* d_in, const int* in_sizes, int n_in,
                              void* d_out, int out_size) {
    const float* x      = (const float*)d_in[0];
    const float* cacheK = (const float*)d_in[1];
    const float* cacheV = (const float*)d_in[2];
    const float* anw    = (const float*)d_in[3];
    const float* qw     = (const float*)d_in[4];
    const float* qb     = (const float*)d_in[5];
    const float* kw     = (const float*)d_in[6];
    const float* kb     = (const float*)d_in[7];
    const float* vw     = (const float*)d_in[8];
    const float* vb     = (const float*)d_in[9];
    const float* ow     = (const float*)d_in[10];
    const float* ob     = (const float*)d_in[11];
    const float* mnw    = (const float*)d_in[12];
    const float* w1     = (const float*)d_in[13];
    const float* b1     = (const float*)d_in[14];
    const float* w2     = (const float*)d_in[15];
    const float* b2     = (const float*)d_in[16];
    const int*   posp   = (const int*)d_in[17];
    float* out = (float*)d_out;

    k_qkv<<<(3 * DIM) / 8, 256>>>(x, anw, qw, qb, kw, kb, vw, vb);
    k_attn<<<NBLK_ATTN, 256>>>(cacheK, cacheV, posp);
    k_attnv_reduce<<<DIM / 32, 256>>>();
    k_oproj<<<DIM / 4, 256>>>(ow, ob, x);
    k_fc1<<<HID / 8, 256>>>(mnw, w1, b1);
    k_fc2<<<DIM / 4, 256>>>(w2, b2, out);
}